// round 1
// baseline (speedup 1.0000x reference)
#include <cuda_runtime.h>

// SideWindowFilter: x [24 planes][768][768] fp32, 5x5 directional kernels, 3 iterations.
// Kernels reduce to: S_left/15, S_right/15, S_top/15, S_bot/15, S_tl/9, S_tl/81, S_bl/9, S_bl/81
// (NE/SE share NW/SW support due to the reference's normalization bug).

#define HH 768
#define WW 768
#define NPLANES 24
#define TW 64
#define TH 32
#define XSW (TW + 4)   // 68
#define XSH (TH + 4)   // 36

__device__ float g_scratch[NPLANES * HH * WW];

__global__ __launch_bounds__(256)
void swf_step(const float* __restrict__ in_ext, float* __restrict__ out_ext,
              int in_is_scratch, int out_is_scratch)
{
    __shared__ float xs[XSH][XSW];   // input tile + halo(2)
    __shared__ float hL[XSH][TW];    // sum over cols j-2..j
    __shared__ float hR[XSH][TW];    // sum over cols j..j+2

    const float* __restrict__ in  = in_is_scratch  ? (const float*)g_scratch : in_ext;
    float* __restrict__       out = out_is_scratch ? (float*)g_scratch       : out_ext;

    const int plane = blockIdx.z;
    const int gx0 = blockIdx.x * TW;
    const int gy0 = blockIdx.y * TH;
    const float* __restrict__ pin = in  + (size_t)plane * HH * WW;
    float* __restrict__ pout      = out + (size_t)plane * HH * WW;

    const int tx = threadIdx.x;      // 0..31
    const int ty = threadIdx.y;      // 0..7
    const int tid = ty * 32 + tx;

    // ---- Phase 1: load tile + halo with zero padding ----
    #pragma unroll
    for (int i = tid; i < XSH * XSW; i += 256) {
        const int r = i / XSW;
        const int c = i - r * XSW;
        const int gy = gy0 + r - 2;
        const int gx = gx0 + c - 2;
        float v = 0.0f;
        if (gy >= 0 && gy < HH && gx >= 0 && gx < WW)
            v = __ldg(&pin[gy * WW + gx]);
        xs[r][c] = v;
    }
    __syncthreads();

    // ---- Phase 2: horizontal 3-sums for all XSH rows ----
    #pragma unroll
    for (int i = tid; i < XSH * TW; i += 256) {
        const int r = i >> 6;        // /64
        const int c = i & 63;
        const float x0 = xs[r][c];
        const float x1 = xs[r][c + 1];
        const float x2 = xs[r][c + 2];
        const float x3 = xs[r][c + 3];
        const float x4 = xs[r][c + 4];
        hL[r][c] = x0 + x1 + x2;     // cols j-2..j
        hR[r][c] = x2 + x3 + x4;     // cols j..j+2
    }
    __syncthreads();

    const float k15 = 1.0f / 15.0f;
    const float k9  = 1.0f / 9.0f;
    const float k81 = 1.0f / 81.0f;

    // ---- Phase 3: 2 cols x 4 consecutive rows per thread, rolling vertical window ----
    #pragma unroll
    for (int cs = 0; cs < 2; cs++) {
        const int c = tx + 32 * cs;        // output col within tile (0..63)
        const int r0 = ty * 4;             // output rows r0..r0+3 (tile coords)

        float a0 = hL[r0 + 0][c], a1 = hL[r0 + 1][c], a2 = hL[r0 + 2][c],
              a3 = hL[r0 + 3][c], a4 = hL[r0 + 4][c];
        float b0 = hR[r0 + 0][c], b1 = hR[r0 + 1][c], b2 = hR[r0 + 2][c],
              b3 = hR[r0 + 3][c], b4 = hR[r0 + 4][c];
        float c0 = xs[r0 + 0][c + 2], c1 = xs[r0 + 1][c + 2], c2 = xs[r0 + 2][c + 2],
              c3 = xs[r0 + 3][c + 2], c4 = xs[r0 + 4][c + 2];

        #pragma unroll
        for (int s = 0; s < 4; s++) {
            const float S_tl   = a0 + a1 + a2;
            const float S_bl   = a2 + a3 + a4;
            const float S_left = S_tl + a3 + a4;
            const float Bt     = b0 + b1 + b2;
            const float Bb     = b2 + b3 + b4;
            const float S_right= Bt + b3 + b4;
            const float Ct     = c0 + c1 + c2;
            const float Cb     = c2 + c3 + c4;
            const float S_top  = S_tl + Bt - Ct;
            const float S_bot  = S_bl + Bb - Cb;
            const float xc     = c2;

            // argmin over |d|, channel order L,R,U,D,NW,NE,SW,SE; strict '<' = first-min tie-break
            float best  = S_left * k15 - xc;
            float bab   = fabsf(best);
            float d, ad;
            d = S_right * k15 - xc; ad = fabsf(d); if (ad < bab) { best = d; bab = ad; }
            d = S_top   * k15 - xc; ad = fabsf(d); if (ad < bab) { best = d; bab = ad; }
            d = S_bot   * k15 - xc; ad = fabsf(d); if (ad < bab) { best = d; bab = ad; }
            d = S_tl    * k9  - xc; ad = fabsf(d); if (ad < bab) { best = d; bab = ad; }
            d = S_tl    * k81 - xc; ad = fabsf(d); if (ad < bab) { best = d; bab = ad; }
            d = S_bl    * k9  - xc; ad = fabsf(d); if (ad < bab) { best = d; bab = ad; }
            d = S_bl    * k81 - xc; ad = fabsf(d); if (ad < bab) { best = d; bab = ad; }

            pout[(size_t)(gy0 + r0 + s) * WW + (gx0 + c)] = xc + best;

            if (s < 3) {
                // roll window down one row
                a0 = a1; a1 = a2; a2 = a3; a3 = a4;
                b0 = b1; b1 = b2; b2 = b3; b3 = b4;
                c0 = c1; c1 = c2; c2 = c3; c3 = c4;
                const int rn = r0 + 5 + s;
                a4 = hL[rn][c];
                b4 = hR[rn][c];
                c4 = xs[rn][c + 2];
            }
        }
    }
}

extern "C" void kernel_launch(void* const* d_in, const int* in_sizes, int n_in,
                              void* d_out, int out_size)
{
    const float* x = (const float*)d_in[0];
    float* out = (float*)d_out;

    const int planes = in_sizes[0] / (HH * WW);   // 24
    dim3 block(32, 8);
    dim3 grid(WW / TW, HH / TH, planes);

    // iteration = 3 (fixed by the problem's setup_inputs)
    // iter 1: x -> out
    swf_step<<<grid, block>>>(x, out, 0, 0);
    // iter 2: out -> scratch
    swf_step<<<grid, block>>>(out, nullptr, 0, 1);
    // iter 3: scratch -> out
    swf_step<<<grid, block>>>(nullptr, out, 1, 0);
}

// round 2
// speedup vs baseline: 1.3366x; 1.3366x over previous
#include <cuda_runtime.h>

// SideWindowFilter: 24 planes of 768x768 fp32, r=2, 3 iterations.
// Directional kernels reduce to 6 box sums per pixel:
//   S_left/15, S_right/15, S_top/15, S_bot/15, S_tl/{9,81}, S_bl/{9,81}
// (NE/SE reuse NW/SW support due to the reference's normalization bug.)

#define HH 768
#define WW 768
#define NPLANES 24
#define TW 64          // tile width  (output cols per block)
#define TH 64          // tile height (output rows per block)
#define RPT 16         // rows per thread (block = 64 x 4 threads)
#define XS 68          // tile + 2*halo

__device__ float g_scratch[NPLANES * HH * WW];

__global__ __launch_bounds__(256)
void swf_step(const float* __restrict__ in_ext, float* __restrict__ out_ext,
              int in_is_scratch, int out_is_scratch)
{
    __shared__ float xs[XS][XS];   // 18.5 KB

    const float* __restrict__ in  = in_is_scratch  ? (const float*)g_scratch : in_ext;
    float* __restrict__       out = out_is_scratch ? (float*)g_scratch       : out_ext;

    const int plane = blockIdx.z;
    const int gx0 = blockIdx.x * TW;
    const int gy0 = blockIdx.y * TH;
    const float* __restrict__ pin = in  + (size_t)plane * HH * WW;
    float* __restrict__ pout      = out + (size_t)plane * HH * WW;

    const int tx = threadIdx.x;      // 0..63  -> output column
    const int ty = threadIdx.y;      // 0..3   -> row group

    // ---- Phase 1: load 68x68 tile (+halo) ----
    const bool interior = (gx0 >= 2) & (gx0 + XS - 2 <= WW) &
                          (gy0 >= 2) & (gy0 + XS - 2 <= HH);
    if (interior) {
        const float* src0 = pin + (size_t)(gy0 - 2) * WW + (gx0 - 2);
        #pragma unroll
        for (int r = ty; r < XS; r += 4) {
            const float* src = src0 + (size_t)r * WW;
            xs[r][tx] = __ldg(&src[tx]);
            if (tx < XS - TW) xs[r][tx + TW] = __ldg(&src[tx + TW]);
        }
    } else {
        #pragma unroll
        for (int r = ty; r < XS; r += 4) {
            const int gy = gy0 - 2 + r;
            const bool yok = (unsigned)gy < HH;
            const int gx1 = gx0 - 2 + tx;
            float v0 = 0.0f, v1 = 0.0f;
            if (yok && (unsigned)gx1 < WW) v0 = __ldg(&pin[(size_t)gy * WW + gx1]);
            xs[r][tx] = v0;
            if (tx < XS - TW) {
                const int gx2 = gx1 + TW;
                if (yok && (unsigned)gx2 < WW) v1 = __ldg(&pin[(size_t)gy * WW + gx2]);
                xs[r][tx + TW] = v1;
            }
        }
    }
    __syncthreads();

    const float k15 = 1.0f / 15.0f;
    const float k9  = 1.0f / 9.0f;
    const float k81 = 1.0f / 81.0f;

    // ---- Phase 2: each thread: 1 column x 16 rows, rolling 5-row windows ----
    const int r0 = ty * RPT;            // first output row (tile coords)
    const int c  = tx;                  // smem window cols c..c+4, center c+2

    // warm-up: rows r0..r0+4 (smem coords), horizontal 3-sums in registers
    float a0, a1, a2, a3, a4;           // sum cols c-2..c   (hL)
    float b0, b1, b2, b3, b4;           // sum cols c..c+2   (hR)
    float c0, c1, c2, c3, c4;           // center col
    {
        float x0, x1, x2, x3, x4;
        x0 = xs[r0+0][c]; x1 = xs[r0+0][c+1]; x2 = xs[r0+0][c+2]; x3 = xs[r0+0][c+3]; x4 = xs[r0+0][c+4];
        a0 = x0 + x1 + x2; b0 = x2 + x3 + x4; c0 = x2;
        x0 = xs[r0+1][c]; x1 = xs[r0+1][c+1]; x2 = xs[r0+1][c+2]; x3 = xs[r0+1][c+3]; x4 = xs[r0+1][c+4];
        a1 = x0 + x1 + x2; b1 = x2 + x3 + x4; c1 = x2;
        x0 = xs[r0+2][c]; x1 = xs[r0+2][c+1]; x2 = xs[r0+2][c+2]; x3 = xs[r0+2][c+3]; x4 = xs[r0+2][c+4];
        a2 = x0 + x1 + x2; b2 = x2 + x3 + x4; c2 = x2;
        x0 = xs[r0+3][c]; x1 = xs[r0+3][c+1]; x2 = xs[r0+3][c+2]; x3 = xs[r0+3][c+3]; x4 = xs[r0+3][c+4];
        a3 = x0 + x1 + x2; b3 = x2 + x3 + x4; c3 = x2;
        x0 = xs[r0+4][c]; x1 = xs[r0+4][c+1]; x2 = xs[r0+4][c+2]; x3 = xs[r0+4][c+3]; x4 = xs[r0+4][c+4];
        a4 = x0 + x1 + x2; b4 = x2 + x3 + x4; c4 = x2;
    }

    float* pw = pout + (size_t)(gy0 + r0) * WW + (gx0 + tx);

    #pragma unroll
    for (int s = 0; s < RPT; s++) {
        const float S_tl = a0 + a1 + a2;
        const float S_bl = a2 + a3 + a4;
        const float S_lf = S_tl + S_bl - a2;
        const float Bt   = b0 + b1 + b2;
        const float Bb   = b2 + b3 + b4;
        const float S_rt = Bt + Bb - b2;
        const float Ct   = c0 + c1 + c2;
        const float Cb   = c2 + c3 + c4;
        const float S_tp = S_tl + Bt - Ct;
        const float S_bt = S_bl + Bb - Cb;
        const float xc   = c2;

        // channel order: L,R,U,D,NW,NE,SW,SE — first-index tie-break
        const float dL  = fmaf(S_lf, k15, -xc);
        const float dR  = fmaf(S_rt, k15, -xc);
        const float dU  = fmaf(S_tp, k15, -xc);
        const float dD  = fmaf(S_bt, k15, -xc);
        const float dNW = fmaf(S_tl, k9,  -xc);
        const float dNE = fmaf(S_tl, k81, -xc);
        const float dSW = fmaf(S_bl, k9,  -xc);
        const float dSE = fmaf(S_bl, k81, -xc);

        // tournament argmin on |d|; lower-index operand kept on ties
        const float m01 = (fabsf(dR)  < fabsf(dL))  ? dR  : dL;
        const float m23 = (fabsf(dD)  < fabsf(dU))  ? dD  : dU;
        const float m45 = (fabsf(dNE) < fabsf(dNW)) ? dNE : dNW;
        const float m67 = (fabsf(dSE) < fabsf(dSW)) ? dSE : dSW;
        const float m03 = (fabsf(m23) < fabsf(m01)) ? m23 : m01;
        const float m47 = (fabsf(m67) < fabsf(m45)) ? m67 : m45;
        const float best = (fabsf(m47) < fabsf(m03)) ? m47 : m03;

        *pw = xc + best;
        pw += WW;

        if (s < RPT - 1) {
            // roll windows down one row
            a0 = a1; a1 = a2; a2 = a3; a3 = a4;
            b0 = b1; b1 = b2; b2 = b3; b3 = b4;
            c0 = c1; c1 = c2; c2 = c3; c3 = c4;
            const int rn = r0 + 5 + s;
            const float x0 = xs[rn][c],     x1 = xs[rn][c+1], x2 = xs[rn][c+2],
                        x3 = xs[rn][c+3],   x4 = xs[rn][c+4];
            a4 = x0 + x1 + x2;
            b4 = x2 + x3 + x4;
            c4 = x2;
        }
    }
}

extern "C" void kernel_launch(void* const* d_in, const int* in_sizes, int n_in,
                              void* d_out, int out_size)
{
    const float* x = (const float*)d_in[0];
    float* out = (float*)d_out;

    dim3 block(64, 4);
    dim3 grid(WW / TW, HH / TH, NPLANES);

    // iteration = 3 (fixed by setup_inputs)
    swf_step<<<grid, block>>>(x, out, 0, 0);        // x       -> out
    swf_step<<<grid, block>>>(out, nullptr, 0, 1);  // out     -> scratch
    swf_step<<<grid, block>>>(nullptr, out, 1, 0);  // scratch -> out
}

// round 4
// speedup vs baseline: 1.3809x; 1.0331x over previous
#include <cuda_runtime.h>

// SideWindowFilter: 24 planes of 768x768 fp32, r=2, 3 iterations.
// Per pixel: 6 box sums -> 8 directional means -> argmin |mean - x| -> x += d.
//   S_left/15, S_right/15, S_top/15, S_bot/15, S_tl/{9,81}, S_bl/{9,81}
// (NE/SE share NW/SW support due to the reference's normalization bug.)

#define HH 768
#define WW 768
#define NPLANES 24
#define TW 64          // tile width
#define TH 64          // tile height
#define RPT 16         // rows per thread; block = (32,4) = 128 threads
#define XS 68          // tile + 2*2 halo

typedef unsigned long long u64;

__device__ float g_scratch[NPLANES * HH * WW];

__device__ __forceinline__ u64 pk(float lo, float hi) {
    u64 r; asm("mov.b64 %0, {%1, %2};" : "=l"(r) : "f"(lo), "f"(hi)); return r;
}
__device__ __forceinline__ u64 fadd2(u64 a, u64 b) {
    u64 r; asm("add.rn.f32x2 %0, %1, %2;" : "=l"(r) : "l"(a), "l"(b)); return r;
}
__device__ __forceinline__ u64 ffma2(u64 a, u64 b, u64 c) {
    u64 r; asm("fma.rn.f32x2 %0, %1, %2, %3;" : "=l"(r) : "l"(a), "l"(b), "l"(c)); return r;
}
__device__ __forceinline__ float2 asf2(u64 v) {
    union { u64 u; float2 f; } cv; cv.u = v; return cv.f;
}

// Build per-row horizontal sums for a 2-col window: loads 6 floats (3 LDS.64).
//   A = {x0+x1+x2, x1+x2+x3}   (left 3-sum per col)
//   B = {x2+x3+x4, x3+x4+x5}   (right 3-sum per col)
//   F = {x0+..+x4, x1+..+x5}   (full 5-sum per col)
//   C = {x2, x3}               (centers)
#define ROWBUILD(rr, A, B, F, C) do {                                   \
    const float2* f2r = (const float2*)xs[rr];                          \
    const float2 p0 = f2r[tx], p1 = f2r[tx + 1], p2 = f2r[tx + 2];      \
    const float u = p0.y + p1.x;                                        \
    const float v = p1.y + p2.x;                                        \
    const float w = u + v;                                              \
    A = pk(u + p0.x, u + p1.y);                                         \
    B = pk(v + p1.x, v + p2.y);                                         \
    F = pk(w + p0.x, w + p2.y);                                         \
    C = pk(p1.x, p1.y);                                                 \
} while (0)

__global__ __launch_bounds__(128)
void swf_step(const float* __restrict__ in_ext, float* __restrict__ out_ext,
              int in_is_scratch, int out_is_scratch)
{
    __shared__ float xs[XS][XS];   // 18.5 KB

    const float* __restrict__ in  = in_is_scratch  ? (const float*)g_scratch : in_ext;
    float* __restrict__       out = out_is_scratch ? (float*)g_scratch       : out_ext;

    const int plane = blockIdx.z;
    const int gx0 = blockIdx.x * TW;
    const int gy0 = blockIdx.y * TH;
    const float* __restrict__ pin = in  + (size_t)plane * HH * WW;
    float* __restrict__ pout      = out + (size_t)plane * HH * WW;

    const int tx = threadIdx.x;      // 0..31 -> col pair 2*tx
    const int ty = threadIdx.y;      // 0..3  -> row group of 16

    // ---- Phase 1: load 68x68 tile (+halo) ----
    const bool interior = (gx0 >= 2) & (gx0 + XS - 2 <= WW) &
                          (gy0 >= 2) & (gy0 + XS - 2 <= HH);
    if (interior) {
        const float* src0 = pin + (size_t)(gy0 - 2) * WW + (gx0 - 2);
        #pragma unroll
        for (int r = ty; r < XS; r += 4) {
            const float* src = src0 + (size_t)r * WW;
            xs[r][tx]      = __ldg(&src[tx]);
            xs[r][tx + 32] = __ldg(&src[tx + 32]);
            if (tx < XS - TW) xs[r][tx + 64] = __ldg(&src[tx + 64]);
        }
    } else {
        #pragma unroll
        for (int r = ty; r < XS; r += 4) {
            const int gy = gy0 - 2 + r;
            const bool yok = (unsigned)gy < HH;
            const int gxa = gx0 - 2 + tx;
            float v0 = 0.0f, v1 = 0.0f;
            if (yok && (unsigned)gxa < WW)        v0 = __ldg(&pin[(size_t)gy * WW + gxa]);
            xs[r][tx] = v0;
            if (yok && (unsigned)(gxa + 32) < WW) v1 = __ldg(&pin[(size_t)gy * WW + gxa + 32]);
            xs[r][tx + 32] = v1;
            if (tx < XS - TW) {
                float v2 = 0.0f;
                if (yok && (unsigned)(gxa + 64) < WW) v2 = __ldg(&pin[(size_t)gy * WW + gxa + 64]);
                xs[r][tx + 64] = v2;
            }
        }
    }
    __syncthreads();

    const u64 K15 = pk(1.0f / 15.0f, 1.0f / 15.0f);
    const u64 K9  = pk(1.0f / 9.0f,  1.0f / 9.0f);
    const u64 K81 = pk(1.0f / 81.0f, 1.0f / 81.0f);

    const int r0 = ty * RPT;   // smem row of first window top (output row r0, smem r0+2)

    // ---- Warm-up: rows r0..r0+4 ----
    u64 A0, A1, A2, A3, A4;
    u64 B0, B1, B2, B3, B4;
    u64 F0, F1, F2, F3, F4;
    u64 Cd, C2, C3, C4;        // centers; only window positions 2..4 needed
    ROWBUILD(r0 + 0, A0, B0, F0, Cd);
    ROWBUILD(r0 + 1, A1, B1, F1, Cd);
    ROWBUILD(r0 + 2, A2, B2, F2, C2);
    ROWBUILD(r0 + 3, A3, B3, F3, C3);
    ROWBUILD(r0 + 4, A4, B4, F4, C4);
    (void)Cd;

    float2* pw = (float2*)(pout + (size_t)(gy0 + r0) * WW + (gx0 + 2 * tx));

    #pragma unroll
    for (int s = 0; s < RPT; s++) {
        const u64 S_tl = fadd2(fadd2(A0, A1), A2);
        const u64 S_bl = fadd2(fadd2(A2, A3), A4);
        const u64 S_lf = fadd2(fadd2(S_tl, A3), A4);
        const u64 S_rt = fadd2(fadd2(fadd2(B0, B1), fadd2(B2, B3)), B4);
        const u64 S_tp = fadd2(fadd2(F0, F1), F2);
        const u64 S_bt = fadd2(fadd2(F2, F3), F4);
        const u64 xc  = C2;
        const u64 nxc = xc ^ 0x8000000080000000ULL;   // packed negate (exact)

        // channel order: L,R,U,D,NW,NE,SW,SE
        const float2 dL  = asf2(ffma2(S_lf, K15, nxc));
        const float2 dR  = asf2(ffma2(S_rt, K15, nxc));
        const float2 dU  = asf2(ffma2(S_tp, K15, nxc));
        const float2 dD  = asf2(ffma2(S_bt, K15, nxc));
        const float2 dNW = asf2(ffma2(S_tl, K9,  nxc));
        const float2 dNE = asf2(ffma2(S_tl, K81, nxc));
        const float2 dSW = asf2(ffma2(S_bl, K9,  nxc));
        const float2 dSE = asf2(ffma2(S_bl, K81, nxc));
        const float2 xcf = asf2(xc);

        // tournament argmin on |d|; strict '<' keeps lower index on ties
        const float a01 = (fabsf(dR.x)  < fabsf(dL.x))  ? dR.x  : dL.x;
        const float a23 = (fabsf(dD.x)  < fabsf(dU.x))  ? dD.x  : dU.x;
        const float a45 = (fabsf(dNE.x) < fabsf(dNW.x)) ? dNE.x : dNW.x;
        const float a67 = (fabsf(dSE.x) < fabsf(dSW.x)) ? dSE.x : dSW.x;
        const float a03 = (fabsf(a23)   < fabsf(a01))   ? a23   : a01;
        const float a47 = (fabsf(a67)   < fabsf(a45))   ? a67   : a45;
        const float best0 = (fabsf(a47) < fabsf(a03))   ? a47   : a03;

        const float b01 = (fabsf(dR.y)  < fabsf(dL.y))  ? dR.y  : dL.y;
        const float b23 = (fabsf(dD.y)  < fabsf(dU.y))  ? dD.y  : dU.y;
        const float b45 = (fabsf(dNE.y) < fabsf(dNW.y)) ? dNE.y : dNW.y;
        const float b67 = (fabsf(dSE.y) < fabsf(dSW.y)) ? dSE.y : dSW.y;
        const float b03 = (fabsf(b23)   < fabsf(b01))   ? b23   : b01;
        const float b47 = (fabsf(b67)   < fabsf(b45))   ? b67   : b45;
        const float best1 = (fabsf(b47) < fabsf(b03))   ? b47   : b03;

        *pw = make_float2(xcf.x + best0, xcf.y + best1);
        pw = (float2*)((float*)pw + WW);

        if (s < RPT - 1) {
            A0 = A1; A1 = A2; A2 = A3; A3 = A4;
            B0 = B1; B1 = B2; B2 = B3; B3 = B4;
            F0 = F1; F1 = F2; F2 = F3; F3 = F4;
            C2 = C3; C3 = C4;
            ROWBUILD(r0 + 5 + s, A4, B4, F4, C4);
        }
    }
}

extern "C" void kernel_launch(void* const* d_in, const int* in_sizes, int n_in,
                              void* d_out, int out_size)
{
    const float* x = (const float*)d_in[0];
    float* out = (float*)d_out;

    dim3 block(32, 4);
    dim3 grid(WW / TW, HH / TH, NPLANES);

    // iteration = 3 (fixed by setup_inputs)
    swf_step<<<grid, block>>>(x, out, 0, 0);        // x       -> out
    swf_step<<<grid, block>>>(out, nullptr, 0, 1);  // out     -> scratch
    swf_step<<<grid, block>>>(nullptr, out, 1, 0);  // scratch -> out
}